// round 1
// baseline (speedup 1.0000x reference)
#include <cuda_runtime.h>
#include <math.h>

#define NN 50000
#define EE 400000
#define DMAX 256

// ---------------- scratch (static device globals; no allocation) ----------------
__device__ float g_h[(size_t)NN * DMAX];     // per-layer projected features
__device__ float g_agg[(size_t)NN * DMAX];   // aggregation accumulator
__device__ float g_x[(size_t)NN * DMAX];     // layer output / next input
__device__ float g_s[NN * 4];
__device__ float g_d[NN * 4];
__device__ float g_m[NN * 4];
__device__ float g_sum[NN * 4];
__device__ float g_aself[NN * 4];
__device__ int g_src[EE];
__device__ int g_dst[EE];
__device__ int g_role[NN];
__device__ int g_is64;

// ---------------- helpers ----------------
__device__ __forceinline__ float warpSum(float v) {
    #pragma unroll
    for (int o = 16; o > 0; o >>= 1) v += __shfl_xor_sync(0xffffffffu, v, o);
    return v;
}

__device__ __forceinline__ void atomicMaxF(float* addr, float value) {
    if (value >= 0.f) atomicMax((int*)addr, __float_as_int(value));
    else              atomicMin((unsigned int*)addr, __float_as_uint(value));
}

__device__ __forceinline__ float leaky(float v) { return v > 0.f ? v : 0.2f * v; }

// ---------------- dtype detect + convert ----------------
__global__ void detect_kernel(const unsigned int* __restrict__ w, int* flag) {
    if (threadIdx.x == 0 && blockIdx.x == 0) {
        int is64 = 1;
        for (int i = 0; i < 64; i++)
            if (w[2 * i + 1] != 0u) { is64 = 0; break; }
        *flag = is64;
    }
}

__global__ void conv_edges_kernel(const void* __restrict__ ei, int* __restrict__ src,
                                  int* __restrict__ dst, const int* __restrict__ flag, int E) {
    int i = blockIdx.x * blockDim.x + threadIdx.x;
    if (i >= E) return;
    if (*flag) {
        const long long* p = (const long long*)ei;
        src[i] = (int)p[i];
        dst[i] = (int)p[(size_t)E + i];
    } else {
        const int* p = (const int*)ei;
        src[i] = p[i];
        dst[i] = p[E + i];
    }
}

__global__ void conv_roles_kernel(const void* __restrict__ rid, int* __restrict__ role,
                                  const int* __restrict__ flag, int n) {
    int i = blockIdx.x * blockDim.x + threadIdx.x;
    if (i >= n) return;
    if (*flag) role[i] = (int)((const long long*)rid)[i];
    else       role[i] = ((const int*)rid)[i];
}

// ---------------- GEMM: C[M,Nc] = A[M,K] * B[Nc,K]^T ----------------
#define BM 64
#define BN 64
#define BK 16
__global__ void gemm_nt(const float* __restrict__ A, const float* __restrict__ B,
                        float* __restrict__ C, int M, int Nc, int K) {
    __shared__ float As[BK][BM + 1];
    __shared__ float Bs[BK][BN + 1];
    int tid = threadIdx.x;           // 256 threads
    int block_row = blockIdx.y * BM;
    int block_col = blockIdx.x * BN;
    int tr = tid / 16, tc = tid % 16;
    float acc[4][4];
    #pragma unroll
    for (int i = 0; i < 4; i++)
        #pragma unroll
        for (int j = 0; j < 4; j++) acc[i][j] = 0.f;

    for (int k0 = 0; k0 < K; k0 += BK) {
        #pragma unroll
        for (int i = 0; i < 4; i++) {
            int li = tid + i * 256;
            int row = li / BK, kk = li % BK;
            int gm = block_row + row;
            As[kk][row] = (gm < M) ? A[(size_t)gm * K + k0 + kk] : 0.f;
        }
        #pragma unroll
        for (int i = 0; i < 4; i++) {
            int li = tid + i * 256;
            int row = li / BK, kk = li % BK;
            int gn = block_col + row;
            Bs[kk][row] = (gn < Nc) ? B[(size_t)gn * K + k0 + kk] : 0.f;
        }
        __syncthreads();
        #pragma unroll
        for (int kk = 0; kk < BK; kk++) {
            float a[4], b[4];
            #pragma unroll
            for (int i = 0; i < 4; i++) a[i] = As[kk][tr * 4 + i];
            #pragma unroll
            for (int j = 0; j < 4; j++) b[j] = Bs[kk][tc * 4 + j];
            #pragma unroll
            for (int i = 0; i < 4; i++)
                #pragma unroll
                for (int j = 0; j < 4; j++) acc[i][j] += a[i] * b[j];
        }
        __syncthreads();
    }
    #pragma unroll
    for (int i = 0; i < 4; i++) {
        int gm = block_row + tr * 4 + i;
        if (gm >= M) continue;
        #pragma unroll
        for (int j = 0; j < 4; j++) {
            int gn = block_col + tc * 4 + j;
            if (gn < Nc) C[(size_t)gm * Nc + gn] = acc[i][j];
        }
    }
}

// ---------------- attention scores: s/d[n,h] = <h[n,h,:], a[h,:]> ----------------
__global__ void score_kernel(const float* __restrict__ h, const float* __restrict__ as_,
                             const float* __restrict__ ad_, float* __restrict__ s_,
                             float* __restrict__ d_, int n, int H, int C) {
    int warp = (blockIdx.x * blockDim.x + threadIdx.x) >> 5;
    int lane = threadIdx.x & 31;
    if (warp >= n * H) return;
    int node = warp / H, hh = warp % H;
    const float* hp = h + (size_t)node * H * C + hh * C;
    float ss = 0.f, dd = 0.f;
    for (int c = lane; c < C; c += 32) {
        float v = hp[c];
        ss += v * as_[hh * C + c];
        dd += v * ad_[hh * C + c];
    }
    ss = warpSum(ss);
    dd = warpSum(dd);
    if (lane == 0) { s_[node * H + hh] = ss; d_[node * H + hh] = dd; }
}

// ---------------- per-(node,head) softmax state ----------------
__global__ void init_m_kernel(const float* __restrict__ s_, const float* __restrict__ d_,
                              float* __restrict__ m_, int total) {
    int i = blockIdx.x * blockDim.x + threadIdx.x;
    if (i >= total) return;
    m_[i] = leaky(s_[i] + d_[i]);   // self loop contribution
}

__global__ void edge_max_kernel(const int* __restrict__ src, const int* __restrict__ dst,
                                const float* __restrict__ s_, const float* __restrict__ d_,
                                float* __restrict__ m_, int E, int H) {
    int idx = blockIdx.x * blockDim.x + threadIdx.x;
    if (idx >= E * H) return;
    int e = idx / H, h = idx % H;
    int a = src[e], b = dst[e];
    float v = leaky(s_[a * H + h] + d_[b * H + h]);
    atomicMaxF(&m_[b * H + h], v);
}

__global__ void init_sum_kernel(const float* __restrict__ s_, const float* __restrict__ d_,
                                const float* __restrict__ m_, float* __restrict__ sum_, int total) {
    int i = blockIdx.x * blockDim.x + threadIdx.x;
    if (i >= total) return;
    sum_[i] = expf(leaky(s_[i] + d_[i]) - m_[i]);  // self loop term
}

__global__ void edge_sum_kernel(const int* __restrict__ src, const int* __restrict__ dst,
                                const float* __restrict__ s_, const float* __restrict__ d_,
                                const float* __restrict__ m_, float* __restrict__ sum_,
                                int E, int H) {
    int idx = blockIdx.x * blockDim.x + threadIdx.x;
    if (idx >= E * H) return;
    int e = idx / H, h = idx % H;
    int a = src[e], b = dst[e];
    float v = leaky(s_[a * H + h] + d_[b * H + h]);
    atomicAdd(&sum_[b * H + h], expf(v - m_[b * H + h]));
}

__global__ void calc_aself_kernel(const float* __restrict__ s_, const float* __restrict__ d_,
                                  const float* __restrict__ m_, const float* __restrict__ sum_,
                                  float* __restrict__ aself, int total) {
    int i = blockIdx.x * blockDim.x + threadIdx.x;
    if (i >= total) return;
    aself[i] = expf(leaky(s_[i] + d_[i]) - m_[i]) / (sum_[i] + 1e-16f);
}

__global__ void init_out_kernel(const float* __restrict__ h, const float* __restrict__ aself,
                                float* __restrict__ agg, int n, int H, int C) {
    int idx = blockIdx.x * blockDim.x + threadIdx.x;
    int D = H * C;
    if (idx >= n * D) return;
    int node = idx / D, c = idx % D;
    int head = c / C;
    agg[idx] = h[idx] * aself[node * H + head];
}

// ---------------- heavy pass: warp per edge, scatter h[src]*alpha into agg[dst] --------
__global__ void edge_aggr_kernel(const int* __restrict__ src, const int* __restrict__ dst,
                                 const float* __restrict__ s_, const float* __restrict__ d_,
                                 const float* __restrict__ m_, const float* __restrict__ sum_,
                                 const float* __restrict__ h, float* __restrict__ agg,
                                 int E, int H, int C) {
    int warp = (blockIdx.x * blockDim.x + threadIdx.x) >> 5;
    int lane = threadIdx.x & 31;
    if (warp >= E) return;
    int a = src[warp], b = dst[warp];
    float alpha = 0.f;
    if (lane < H) {
        float e = leaky(s_[a * H + lane] + d_[b * H + lane]);
        alpha = expf(e - m_[b * H + lane]) / (sum_[b * H + lane] + 1e-16f);
    }
    int D = H * C;
    int nf4 = D >> 2;
    const float4* hp = (const float4*)(h + (size_t)a * D);
    float* op = agg + (size_t)b * D;
    for (int it = 0; it * 32 < nf4; it++) {
        int f = lane + it * 32;
        int fc = f < nf4 ? f : (nf4 - 1);
        int head = (fc << 2) / C;
        float al = __shfl_sync(0xffffffffu, alpha, head);
        if (f < nf4) {
            float4 v = hp[f];
            atomicAdd(op + f * 4 + 0, v.x * al);
            atomicAdd(op + f * 4 + 1, v.y * al);
            atomicAdd(op + f * 4 + 2, v.z * al);
            atomicAdd(op + f * 4 + 3, v.w * al);
        }
    }
}

// ---------------- epilogue: bias (+elu) + layernorm; warp per node ----------------
__global__ void epilogue_kernel(const float* __restrict__ agg, const float* __restrict__ bias,
                                const float* __restrict__ lw, const float* __restrict__ lb,
                                float* __restrict__ outp, int n, int D, int do_elu) {
    int warp = (blockIdx.x * blockDim.x + threadIdx.x) >> 5;
    int lane = threadIdx.x & 31;
    if (warp >= n) return;
    const float* row = agg + (size_t)warp * D;
    float vals[8];
    int nv = D >> 5;
    float s = 0.f;
    for (int i = 0; i < nv; i++) {
        int c = lane + i * 32;
        float v = row[c] + bias[c];
        if (do_elu) v = v > 0.f ? v : (expf(v) - 1.f);
        vals[i] = v;
        s += v;
    }
    s = warpSum(s);
    float mu = s / (float)D;
    float vs = 0.f;
    for (int i = 0; i < nv; i++) { float t = vals[i] - mu; vs += t * t; }
    vs = warpSum(vs);
    float rs = rsqrtf(vs / (float)D + 1e-5f);
    float* orow = outp + (size_t)warp * D;
    for (int i = 0; i < nv; i++) {
        int c = lane + i * 32;
        orow[c] = (vals[i] - mu) * rs * lw[c] + lb[c];
    }
}

// ---------------- final MLP head ----------------
// z = concat(h3, role_emb) [128]; z1 = relu(p1w z + p1b) [64]; out = p2w z1 + p2b [64]
__global__ void head_kernel(const float* __restrict__ h3, const int* __restrict__ role,
                            const float* __restrict__ rt, const float* __restrict__ p1w,
                            const float* __restrict__ p1b, const float* __restrict__ p2w,
                            const float* __restrict__ p2b, float* __restrict__ z, int n) {
    extern __shared__ float sm[];
    float* sp1 = sm;                 // 128*64 transposed: sp1[k*64+j] = p1w[j*128+k]
    float* sp2 = sp1 + 128 * 64;     // 64*64 transposed: sp2[k*64+j] = p2w[j*64+k]
    float* sz  = sp2 + 64 * 64;      // 4 groups * 128
    float* sz1 = sz + 4 * 128;       // 4 groups * 64
    int tid = threadIdx.x;
    for (int i = tid; i < 128 * 64; i += 256) {
        int j = i / 128, k = i % 128;
        sp1[k * 64 + j] = p1w[i];
    }
    for (int i = tid; i < 64 * 64; i += 256) {
        int j = i / 64, k = i % 64;
        sp2[k * 64 + j] = p2w[i];
    }
    __syncthreads();
    int g = tid >> 6, j = tid & 63;
    float b1v = p1b[j], b2v = p2b[j];
    for (int it = 0; it < 16; it++) {
        int node = blockIdx.x * 64 + it * 4 + g;
        bool valid = node < n;
        if (valid) {
            sz[g * 128 + j] = h3[(size_t)node * 64 + j];
            int r = role[node];
            sz[g * 128 + 64 + j] = rt[r * 64 + j];
        }
        __syncthreads();
        float acc = b1v;
        #pragma unroll 8
        for (int k = 0; k < 128; k++) acc += sp1[k * 64 + j] * sz[g * 128 + k];
        sz1[g * 64 + j] = fmaxf(acc, 0.f);
        __syncthreads();
        float acc2 = b2v;
        #pragma unroll 8
        for (int k = 0; k < 64; k++) acc2 += sp2[k * 64 + j] * sz1[g * 64 + k];
        if (valid) z[(size_t)node * 64 + j] = acc2;
    }
}

// ---------------- host orchestration ----------------
static void run_layer(const float* in, int Fin, int H, int C,
                      const float* W, const float* as_, const float* ad_, const float* bias,
                      const float* lw, const float* lb, int do_elu,
                      float* hbuf, float* aggbuf, float* outbuf,
                      float* sp, float* dp, float* mp, float* sump, float* aselfp,
                      int* srcp, int* dstp) {
    const int n = NN, E = EE;
    int D = H * C;
    dim3 ggrid((D + BM - 1) / BN, (n + BM - 1) / BM);
    gemm_nt<<<ggrid, 256>>>(in, W, hbuf, n, D, Fin);
    score_kernel<<<(n * H * 32 + 255) / 256, 256>>>(hbuf, as_, ad_, sp, dp, n, H, C);
    init_m_kernel<<<(n * H + 255) / 256, 256>>>(sp, dp, mp, n * H);
    edge_max_kernel<<<(E * H + 255) / 256, 256>>>(srcp, dstp, sp, dp, mp, E, H);
    init_sum_kernel<<<(n * H + 255) / 256, 256>>>(sp, dp, mp, sump, n * H);
    edge_sum_kernel<<<(E * H + 255) / 256, 256>>>(srcp, dstp, sp, dp, mp, sump, E, H);
    calc_aself_kernel<<<(n * H + 255) / 256, 256>>>(sp, dp, mp, sump, aselfp, n * H);
    init_out_kernel<<<(n * D + 255) / 256, 256>>>(hbuf, aselfp, aggbuf, n, H, C);
    edge_aggr_kernel<<<(E * 32 + 255) / 256, 256>>>(srcp, dstp, sp, dp, mp, sump, hbuf, aggbuf, E, H, C);
    epilogue_kernel<<<(n * 32 + 255) / 256, 256>>>(aggbuf, bias, lw, lb, outbuf, n, D, do_elu);
}

extern "C" void kernel_launch(void* const* d_in, const int* in_sizes, int n_in,
                              void* d_out, int out_size) {
    const float* x   = (const float*)d_in[0];
    const void*  ei  = d_in[1];
    const void*  rid = d_in[2];
    const float* W1  = (const float*)d_in[3];
    const float* a1s = (const float*)d_in[4];
    const float* a1d = (const float*)d_in[5];
    const float* b1  = (const float*)d_in[6];
    const float* W2  = (const float*)d_in[7];
    const float* a2s = (const float*)d_in[8];
    const float* a2d = (const float*)d_in[9];
    const float* b2  = (const float*)d_in[10];
    const float* W3  = (const float*)d_in[11];
    const float* a3s = (const float*)d_in[12];
    const float* a3d = (const float*)d_in[13];
    const float* b3  = (const float*)d_in[14];
    const float* ln1w = (const float*)d_in[15];
    const float* ln1b = (const float*)d_in[16];
    const float* ln2w = (const float*)d_in[17];
    const float* ln2b = (const float*)d_in[18];
    const float* ln3w = (const float*)d_in[19];
    const float* ln3b = (const float*)d_in[20];
    const float* rt   = (const float*)d_in[21];
    const float* p1w  = (const float*)d_in[22];
    const float* p1b  = (const float*)d_in[23];
    const float* p2w  = (const float*)d_in[24];
    const float* p2b  = (const float*)d_in[25];
    float* z = (float*)d_out;

    float *hbuf, *aggbuf, *xbuf, *sp, *dp, *mp, *sump, *aselfp;
    int *srcp, *dstp, *rolep, *flagp;
    cudaGetSymbolAddress((void**)&hbuf, g_h);
    cudaGetSymbolAddress((void**)&aggbuf, g_agg);
    cudaGetSymbolAddress((void**)&xbuf, g_x);
    cudaGetSymbolAddress((void**)&sp, g_s);
    cudaGetSymbolAddress((void**)&dp, g_d);
    cudaGetSymbolAddress((void**)&mp, g_m);
    cudaGetSymbolAddress((void**)&sump, g_sum);
    cudaGetSymbolAddress((void**)&aselfp, g_aself);
    cudaGetSymbolAddress((void**)&srcp, g_src);
    cudaGetSymbolAddress((void**)&dstp, g_dst);
    cudaGetSymbolAddress((void**)&rolep, g_role);
    cudaGetSymbolAddress((void**)&flagp, g_is64);

    const int n = NN, E = EE;

    detect_kernel<<<1, 32>>>((const unsigned int*)ei, flagp);
    conv_edges_kernel<<<(E + 255) / 256, 256>>>(ei, srcp, dstp, flagp, E);
    conv_roles_kernel<<<(n + 255) / 256, 256>>>(rid, rolep, flagp, n);

    // layer 1: 64 -> 4x64 concat, elu + LN
    run_layer(x, 64, 4, 64, W1, a1s, a1d, b1, ln1w, ln1b, 1,
              hbuf, aggbuf, xbuf, sp, dp, mp, sump, aselfp, srcp, dstp);
    // layer 2: 256 -> 4x64 concat, elu + LN
    run_layer(xbuf, 256, 4, 64, W2, a2s, a2d, b2, ln2w, ln2b, 1,
              hbuf, aggbuf, xbuf, sp, dp, mp, sump, aselfp, srcp, dstp);
    // layer 3: 256 -> 1x64 (mean over 1 head == identity), LN only
    run_layer(xbuf, 256, 1, 64, W3, a3s, a3d, b3, ln3w, ln3b, 0,
              hbuf, aggbuf, hbuf, sp, dp, mp, sump, aselfp, srcp, dstp);

    // final MLP head
    size_t smem = (128 * 64 + 64 * 64 + 4 * 128 + 4 * 64) * sizeof(float);
    cudaFuncSetAttribute(head_kernel, cudaFuncAttributeMaxDynamicSharedMemorySize, (int)smem);
    head_kernel<<<(n + 63) / 64, 256, smem>>>(hbuf, rolep, rt, p1w, p1b, p2w, p2b, z, n);
}

// round 2
// speedup vs baseline: 1.8832x; 1.8832x over previous
#include <cuda_runtime.h>
#include <math.h>

#define NN 50000
#define EE 400000
#define DMAX 256

// ---------------- scratch (static device globals; no allocation) ----------------
__device__ float g_h[(size_t)NN * DMAX];     // projected features
__device__ float g_x[(size_t)NN * DMAX];     // layer output / next input
__device__ float g_y[(size_t)NN * DMAX];     // layer-3 output
__device__ float g_s[NN * 4];
__device__ float g_d[NN * 4];
__device__ int g_src[EE];
__device__ int g_dst[EE];
__device__ int g_ecol[EE];                   // CSR col indices (src per dst-row)
__device__ int g_rowptr[NN + 1];
__device__ int g_deg[NN];
__device__ int g_cursor[NN];
__device__ int g_role[NN];
__device__ int g_is64;

// ---------------- helpers ----------------
__device__ __forceinline__ float warpSum(float v) {
    #pragma unroll
    for (int o = 16; o > 0; o >>= 1) v += __shfl_xor_sync(0xffffffffu, v, o);
    return v;
}
__device__ __forceinline__ float leaky(float v) { return v > 0.f ? v : 0.2f * v; }

// ---------------- dtype detect + convert ----------------
__global__ void detect_kernel(const unsigned int* __restrict__ w, int* flag) {
    if (threadIdx.x == 0 && blockIdx.x == 0) {
        int is64 = 1;
        for (int i = 0; i < 64; i++)
            if (w[2 * i + 1] != 0u) { is64 = 0; break; }
        *flag = is64;
    }
}

__global__ void conv_edges_kernel(const void* __restrict__ ei, int* __restrict__ src,
                                  int* __restrict__ dst, const int* __restrict__ flag, int E) {
    int i = blockIdx.x * blockDim.x + threadIdx.x;
    if (i >= E) return;
    if (*flag) {
        const long long* p = (const long long*)ei;
        src[i] = (int)p[i];
        dst[i] = (int)p[(size_t)E + i];
    } else {
        const int* p = (const int*)ei;
        src[i] = p[i];
        dst[i] = p[E + i];
    }
}

__global__ void conv_roles_kernel(const void* __restrict__ rid, int* __restrict__ role,
                                  const int* __restrict__ flag, int n) {
    int i = blockIdx.x * blockDim.x + threadIdx.x;
    if (i >= n) return;
    if (*flag) role[i] = (int)((const long long*)rid)[i];
    else       role[i] = ((const int*)rid)[i];
}

// ---------------- CSR build ----------------
__global__ void zero_deg_kernel(int* __restrict__ deg, int n) {
    int i = blockIdx.x * blockDim.x + threadIdx.x;
    if (i < n) deg[i] = 0;
}

__global__ void hist_kernel(const int* __restrict__ dst, int* __restrict__ deg, int E) {
    int i = blockIdx.x * blockDim.x + threadIdx.x;
    if (i < E) atomicAdd(&deg[dst[i]], 1);
}

// single-block inclusive-scan driven exclusive rowptr
__global__ void scan_kernel(const int* __restrict__ deg, int* __restrict__ rowptr, int n) {
    __shared__ int sh[1024];
    __shared__ int offset;
    int tid = threadIdx.x;
    if (tid == 0) offset = 0;
    __syncthreads();
    for (int base = 0; base < n; base += 1024) {
        int i = base + tid;
        int v = (i < n) ? deg[i] : 0;
        sh[tid] = v;
        __syncthreads();
        #pragma unroll
        for (int s = 1; s < 1024; s <<= 1) {
            int t = (tid >= s) ? sh[tid - s] : 0;
            __syncthreads();
            sh[tid] += t;
            __syncthreads();
        }
        if (i < n) rowptr[i + 1] = offset + sh[tid];
        __syncthreads();
        if (tid == 1023) offset += sh[1023];
        __syncthreads();
    }
    if (tid == 0) rowptr[0] = 0;
}

__global__ void copy_cursor_kernel(const int* __restrict__ rowptr, int* __restrict__ cursor, int n) {
    int i = blockIdx.x * blockDim.x + threadIdx.x;
    if (i < n) cursor[i] = rowptr[i];
}

__global__ void scatter_kernel(const int* __restrict__ src, const int* __restrict__ dst,
                               int* __restrict__ cursor, int* __restrict__ ecol, int E) {
    int i = blockIdx.x * blockDim.x + threadIdx.x;
    if (i >= E) return;
    int pos = atomicAdd(&cursor[dst[i]], 1);
    ecol[pos] = src[i];
}

// ---------------- GEMM: C[M,Nc] = A[M,K] * B[Nc,K]^T  (128x64x16 tiles) ----------------
#define GBM 128
#define GBN 64
#define GBK 16
__global__ void gemm_nt(const float* __restrict__ A, const float* __restrict__ B,
                        float* __restrict__ C, int M, int Nc, int K) {
    __shared__ float As[GBK][GBM + 4];
    __shared__ float Bs[GBK][GBN + 4];
    int tid = threadIdx.x;                       // 256 threads
    int brow = blockIdx.y * GBM;
    int bcol = blockIdx.x * GBN;
    int tr = tid >> 4, tc = tid & 15;
    float acc[8][4];
    #pragma unroll
    for (int i = 0; i < 8; i++)
        #pragma unroll
        for (int j = 0; j < 4; j++) acc[i][j] = 0.f;

    for (int k0 = 0; k0 < K; k0 += GBK) {
        #pragma unroll
        for (int t = 0; t < 2; t++) {
            int li = tid + t * 256;              // 512 float4 loads for A
            int row = li >> 2, kq = (li & 3) * 4;
            int gm = brow + row;
            float4 v = make_float4(0.f, 0.f, 0.f, 0.f);
            if (gm < M) v = *(const float4*)&A[(size_t)gm * K + k0 + kq];
            As[kq + 0][row] = v.x; As[kq + 1][row] = v.y;
            As[kq + 2][row] = v.z; As[kq + 3][row] = v.w;
        }
        {
            int li = tid;                        // 256 float4 loads for B
            int row = li >> 2, kq = (li & 3) * 4;
            int gn = bcol + row;
            float4 v = make_float4(0.f, 0.f, 0.f, 0.f);
            if (gn < Nc) v = *(const float4*)&B[(size_t)gn * K + k0 + kq];
            Bs[kq + 0][row] = v.x; Bs[kq + 1][row] = v.y;
            Bs[kq + 2][row] = v.z; Bs[kq + 3][row] = v.w;
        }
        __syncthreads();
        #pragma unroll
        for (int kk = 0; kk < GBK; kk++) {
            float a[8], b[4];
            *(float4*)&a[0] = *(float4*)&As[kk][tr * 8];
            *(float4*)&a[4] = *(float4*)&As[kk][tr * 8 + 4];
            *(float4*)&b[0] = *(float4*)&Bs[kk][tc * 4];
            #pragma unroll
            for (int i = 0; i < 8; i++)
                #pragma unroll
                for (int j = 0; j < 4; j++) acc[i][j] += a[i] * b[j];
        }
        __syncthreads();
    }
    #pragma unroll
    for (int i = 0; i < 8; i++) {
        int gm = brow + tr * 8 + i;
        if (gm >= M) continue;
        #pragma unroll
        for (int j = 0; j < 4; j++) {
            int gn = bcol + tc * 4 + j;
            if (gn < Nc) C[(size_t)gm * Nc + gn] = acc[i][j];
        }
    }
}

// ---------------- attention scores ----------------
__global__ void score_kernel(const float* __restrict__ h, const float* __restrict__ as_,
                             const float* __restrict__ ad_, float* __restrict__ s_,
                             float* __restrict__ d_, int n, int H, int C) {
    int warp = (blockIdx.x * blockDim.x + threadIdx.x) >> 5;
    int lane = threadIdx.x & 31;
    if (warp >= n * H) return;
    int node = warp / H, hh = warp % H;
    const float* hp = h + (size_t)node * H * C + hh * C;
    float ss = 0.f, dd = 0.f;
    for (int c = lane; c < C; c += 32) {
        float v = hp[c];
        ss += v * as_[hh * C + c];
        dd += v * ad_[hh * C + c];
    }
    ss = warpSum(ss);
    dd = warpSum(dd);
    if (lane == 0) { s_[node * H + hh] = ss; d_[node * H + hh] = dd; }
}

// ---------------- fused per-dst: softmax + aggregate + bias/ELU + LayerNorm ------------
// warp per dst node; NV = H*64/32 registers of accumulation per lane.
template<int H>
__global__ void gat_fused(const int* __restrict__ rowptr, const int* __restrict__ ecol,
                          const float* __restrict__ s_, const float* __restrict__ d_,
                          const float* __restrict__ h, const float* __restrict__ bias,
                          const float* __restrict__ lw, const float* __restrict__ lb,
                          float* __restrict__ outp, int n, int do_elu) {
    const int D = H * 64;
    const int NV = D / 32;
    int warp = (blockIdx.x * blockDim.x + threadIdx.x) >> 5;
    int lane = threadIdx.x & 31;
    if (warp >= n) return;
    int node = warp;
    int start = rowptr[node], end = rowptr[node + 1];

    // self scores
    float dsel[H], selfv[H];
    #pragma unroll
    for (int q = 0; q < H; q++) {
        float sv = s_[(size_t)node * H + q];
        float dv = d_[(size_t)node * H + q];
        dsel[q] = dv;
        selfv[q] = leaky(sv + dv);
    }
    // sweep 1: max (self included)
    float mx[H];
    #pragma unroll
    for (int q = 0; q < H; q++) mx[q] = selfv[q];
    for (int e = start + lane; e < end; e += 32) {
        int src = ecol[e];
        #pragma unroll
        for (int q = 0; q < H; q++) {
            float v = leaky(s_[(size_t)src * H + q] + dsel[q]);
            mx[q] = fmaxf(mx[q], v);
        }
    }
    #pragma unroll
    for (int q = 0; q < H; q++)
        #pragma unroll
        for (int o = 16; o > 0; o >>= 1) mx[q] = fmaxf(mx[q], __shfl_xor_sync(0xffffffffu, mx[q], o));

    // sweep 2: sum of exp
    float sm[H];
    #pragma unroll
    for (int q = 0; q < H; q++) sm[q] = 0.f;
    for (int e = start + lane; e < end; e += 32) {
        int src = ecol[e];
        #pragma unroll
        for (int q = 0; q < H; q++) {
            float v = leaky(s_[(size_t)src * H + q] + dsel[q]);
            sm[q] += expf(v - mx[q]);
        }
    }
    float inv[H], aself[H];
    #pragma unroll
    for (int q = 0; q < H; q++) {
        float tot = warpSum(sm[q]) + expf(selfv[q] - mx[q]);   // self term
        inv[q] = 1.f / (tot + 1e-16f);
        aself[q] = expf(selfv[q] - mx[q]) * inv[q];
    }

    // per-lane head assignment for alpha computation (4 lanes per edge)
    int hl = lane & 3;
    float d_hl, m_hl, i_hl;
    if (H == 4) {
        d_hl = (hl == 0) ? dsel[0] : (hl == 1) ? dsel[1] : (hl == 2) ? dsel[2] : dsel[3];
        m_hl = (hl == 0) ? mx[0]   : (hl == 1) ? mx[1]   : (hl == 2) ? mx[2]   : mx[3];
        i_hl = (hl == 0) ? inv[0]  : (hl == 1) ? inv[1]  : (hl == 2) ? inv[2]  : inv[3];
    } else {
        d_hl = dsel[0]; m_hl = mx[0]; i_hl = inv[0];
    }

    // accumulate: init with self loop
    float accv[NV];
    const float* hps = h + (size_t)node * D;
    #pragma unroll
    for (int i = 0; i < NV; i++) accv[i] = hps[lane + i * 32] * aself[i >> 1];

    for (int e0 = start; e0 < end; e0 += 8) {
        int me = e0 + (lane >> 2);
        float alpha = 0.f;
        int msrc = 0;
        if (me < end && hl < H) {
            msrc = ecol[me];
            float v = leaky(s_[(size_t)msrc * H + hl] + d_hl);
            alpha = expf(v - m_hl) * i_hl;
        }
        int cnt = end - e0; if (cnt > 8) cnt = 8;
        for (int j = 0; j < cnt; j++) {
            int src = __shfl_sync(0xffffffffu, msrc, j * 4);
            const float* hp = h + (size_t)src * D;
            #pragma unroll
            for (int i = 0; i < NV; i++) {
                float al = __shfl_sync(0xffffffffu, alpha, j * 4 + (i >> 1));
                accv[i] += hp[lane + i * 32] * al;
            }
        }
    }

    // epilogue: bias (+elu) + layernorm
    float ssum = 0.f;
    #pragma unroll
    for (int i = 0; i < NV; i++) {
        int c = lane + i * 32;
        float v = accv[i] + bias[c];
        if (do_elu) v = v > 0.f ? v : (expf(v) - 1.f);
        accv[i] = v;
        ssum += v;
    }
    ssum = warpSum(ssum);
    float mu = ssum / (float)D;
    float vs = 0.f;
    #pragma unroll
    for (int i = 0; i < NV; i++) { float t = accv[i] - mu; vs += t * t; }
    vs = warpSum(vs);
    float rs = rsqrtf(vs / (float)D + 1e-5f);
    float* orow = outp + (size_t)node * D;
    #pragma unroll
    for (int i = 0; i < NV; i++) {
        int c = lane + i * 32;
        orow[c] = (accv[i] - mu) * rs * lw[c] + lb[c];
    }
}

// ---------------- final MLP head ----------------
__global__ void head_kernel(const float* __restrict__ h3, const int* __restrict__ role,
                            const float* __restrict__ rt, const float* __restrict__ p1w,
                            const float* __restrict__ p1b, const float* __restrict__ p2w,
                            const float* __restrict__ p2b, float* __restrict__ z, int n) {
    extern __shared__ float sm[];
    float* sp1 = sm;                 // 128*64 transposed
    float* sp2 = sp1 + 128 * 64;     // 64*64 transposed
    float* sz  = sp2 + 64 * 64;      // 4 groups * 128
    float* sz1 = sz + 4 * 128;       // 4 groups * 64
    int tid = threadIdx.x;
    for (int i = tid; i < 128 * 64; i += 256) {
        int j = i / 128, k = i % 128;
        sp1[k * 64 + j] = p1w[i];
    }
    for (int i = tid; i < 64 * 64; i += 256) {
        int j = i / 64, k = i % 64;
        sp2[k * 64 + j] = p2w[i];
    }
    __syncthreads();
    int g = tid >> 6, j = tid & 63;
    float b1v = p1b[j], b2v = p2b[j];
    for (int it = 0; it < 16; it++) {
        int node = blockIdx.x * 64 + it * 4 + g;
        bool valid = node < n;
        if (valid) {
            sz[g * 128 + j] = h3[(size_t)node * 64 + j];
            int r = role[node];
            sz[g * 128 + 64 + j] = rt[r * 64 + j];
        }
        __syncthreads();
        float acc = b1v;
        #pragma unroll 8
        for (int k = 0; k < 128; k++) acc += sp1[k * 64 + j] * sz[g * 128 + k];
        sz1[g * 64 + j] = fmaxf(acc, 0.f);
        __syncthreads();
        float acc2 = b2v;
        #pragma unroll 8
        for (int k = 0; k < 64; k++) acc2 += sp2[k * 64 + j] * sz1[g * 64 + k];
        if (valid) z[(size_t)node * 64 + j] = acc2;
    }
}

// ---------------- host orchestration ----------------
extern "C" void kernel_launch(void* const* d_in, const int* in_sizes, int n_in,
                              void* d_out, int out_size) {
    const float* x   = (const float*)d_in[0];
    const void*  ei  = d_in[1];
    const void*  rid = d_in[2];
    const float* W1  = (const float*)d_in[3];
    const float* a1s = (const float*)d_in[4];
    const float* a1d = (const float*)d_in[5];
    const float* b1  = (const float*)d_in[6];
    const float* W2  = (const float*)d_in[7];
    const float* a2s = (const float*)d_in[8];
    const float* a2d = (const float*)d_in[9];
    const float* b2  = (const float*)d_in[10];
    const float* W3  = (const float*)d_in[11];
    const float* a3s = (const float*)d_in[12];
    const float* a3d = (const float*)d_in[13];
    const float* b3  = (const float*)d_in[14];
    const float* ln1w = (const float*)d_in[15];
    const float* ln1b = (const float*)d_in[16];
    const float* ln2w = (const float*)d_in[17];
    const float* ln2b = (const float*)d_in[18];
    const float* ln3w = (const float*)d_in[19];
    const float* ln3b = (const float*)d_in[20];
    const float* rt   = (const float*)d_in[21];
    const float* p1w  = (const float*)d_in[22];
    const float* p1b  = (const float*)d_in[23];
    const float* p2w  = (const float*)d_in[24];
    const float* p2b  = (const float*)d_in[25];
    float* z = (float*)d_out;

    float *hbuf, *xbuf, *ybuf, *sp, *dp;
    int *srcp, *dstp, *ecolp, *rowp, *degp, *curp, *rolep, *flagp;
    cudaGetSymbolAddress((void**)&hbuf, g_h);
    cudaGetSymbolAddress((void**)&xbuf, g_x);
    cudaGetSymbolAddress((void**)&ybuf, g_y);
    cudaGetSymbolAddress((void**)&sp, g_s);
    cudaGetSymbolAddress((void**)&dp, g_d);
    cudaGetSymbolAddress((void**)&srcp, g_src);
    cudaGetSymbolAddress((void**)&dstp, g_dst);
    cudaGetSymbolAddress((void**)&ecolp, g_ecol);
    cudaGetSymbolAddress((void**)&rowp, g_rowptr);
    cudaGetSymbolAddress((void**)&degp, g_deg);
    cudaGetSymbolAddress((void**)&curp, g_cursor);
    cudaGetSymbolAddress((void**)&rolep, g_role);
    cudaGetSymbolAddress((void**)&flagp, g_is64);

    const int n = NN, E = EE;

    // index conversion + CSR build
    detect_kernel<<<1, 32>>>((const unsigned int*)ei, flagp);
    conv_edges_kernel<<<(E + 255) / 256, 256>>>(ei, srcp, dstp, flagp, E);
    conv_roles_kernel<<<(n + 255) / 256, 256>>>(rid, rolep, flagp, n);
    zero_deg_kernel<<<(n + 255) / 256, 256>>>(degp, n);
    hist_kernel<<<(E + 255) / 256, 256>>>(dstp, degp, E);
    scan_kernel<<<1, 1024>>>(degp, rowp, n);
    copy_cursor_kernel<<<(n + 255) / 256, 256>>>(rowp, curp, n);
    scatter_kernel<<<(E + 255) / 256, 256>>>(srcp, dstp, curp, ecolp, E);

    dim3 g1((256 + GBN - 1) / GBN, (n + GBM - 1) / GBM);
    dim3 g3((64 + GBN - 1) / GBN, (n + GBM - 1) / GBM);
    int fusedBlocks = (n * 32 + 255) / 256;

    // layer 1: 64 -> 4x64 concat, elu + LN
    gemm_nt<<<g1, 256>>>(x, W1, hbuf, n, 256, 64);
    score_kernel<<<(n * 4 * 32 + 255) / 256, 256>>>(hbuf, a1s, a1d, sp, dp, n, 4, 64);
    gat_fused<4><<<fusedBlocks, 256>>>(rowp, ecolp, sp, dp, hbuf, b1, ln1w, ln1b, xbuf, n, 1);

    // layer 2: 256 -> 4x64 concat, elu + LN
    gemm_nt<<<g1, 256>>>(xbuf, W2, hbuf, n, 256, 256);
    score_kernel<<<(n * 4 * 32 + 255) / 256, 256>>>(hbuf, a2s, a2d, sp, dp, n, 4, 64);
    gat_fused<4><<<fusedBlocks, 256>>>(rowp, ecolp, sp, dp, hbuf, b2, ln2w, ln2b, xbuf, n, 1);

    // layer 3: 256 -> 1x64 (single head), LN only
    gemm_nt<<<g3, 256>>>(xbuf, W3, hbuf, n, 64, 256);
    score_kernel<<<(n * 1 * 32 + 255) / 256, 256>>>(hbuf, a3s, a3d, sp, dp, n, 1, 64);
    gat_fused<1><<<fusedBlocks, 256>>>(rowp, ecolp, sp, dp, hbuf, b3, ln3w, ln3b, ybuf, n, 0);

    // final MLP head
    size_t smem = (128 * 64 + 64 * 64 + 4 * 128 + 4 * 64) * sizeof(float);
    cudaFuncSetAttribute(head_kernel, cudaFuncAttributeMaxDynamicSharedMemorySize, (int)smem);
    head_kernel<<<(n + 63) / 64, 256, smem>>>(ybuf, rolep, rt, p1w, p1b, p2w, p2b, z, n);
}